// round 12
// baseline (speedup 1.0000x reference)
#include <cuda_runtime.h>
#include <math_constants.h>

// Problem constants (fixed by the dataset)
#define NG      512     // graphs
#define N_PER   256     // nodes per graph
#define DD      128     // embed dim
#define E_PER   4096    // edges per graph
#define KK      128     // kept nodes per graph
#define GT      256     // threads per graph-group (half CTA)
#define CTA_T   512     // threads per CTA (2 pipelines)
#define GRID_B  296     // 2 CTAs per SM x 148 SMs: every SM hosts 4 pipelines
#define MAXB    36      // bucket capacity (max in-degree w/o overflow)
#define BSTR    40      // bucket row stride in ushorts (80 B, 16B-aligned rows)
#define OVF_CAP 256     // overflow edge list capacity

// Global work queue cursor (reset by a tiny kernel before the main launch).
__device__ int g_next;

// Per-pipeline shared state. float4 arrays first for alignment.
struct SmemHalf {
    float4 psum4[8][DD / 4];           // 4 KB (pooling + epilogue partials)
    float4 pmax4[8][DD / 4];           // 4 KB
    unsigned short bkt[N_PER * BSTR];  // 20.5 KB CSR buckets (16B-aligned rows)
    int   cnt[N_PER];                  // in-degree / cursor / histogram
    float xwp[N_PER];                  // xw, then xw*dinv
    float dinv[N_PER];
    float agg[N_PER];                  // edge sum, then score
    float gate[N_PER];
    unsigned int   m[N_PER];           // sortable score keys
    float read[2 * DD];                // readout [mean | max]
    int   ovf[OVF_CAP];                // packed (dst<<16)|src
    unsigned short cand[N_PER];        // boundary candidates
    unsigned short kept[KK];           // compacted kept node ids
    int   woff[8];                     // per-warp compaction offsets
    int   sel[5];                      // b1, r1, b2, r2, candn
    int   ovfn;
    int   gid;                         // fetched graph id
};

// Named barrier over one 256-thread pipeline (ids 1 and 2).
#define GBAR(id) asm volatile("bar.sync %0, %1;" :: "r"(id), "r"(GT) : "memory")

// Warp-0-of-half helper: given hist[256], find bucket b* and residual r such
// that suffix(b*+1) < target <= suffix(b*);  r = target - suffix(b*+1).
__device__ __forceinline__ void radix_scan256(const int* hist, int target,
                                              int* out_b, int* out_r, int lane)
{
    int s = 0;
    #pragma unroll
    for (int j = 0; j < 8; ++j) s += hist[lane * 8 + j];
    int suf = s;                                    // inclusive suffix over chunks
    #pragma unroll
    for (int off = 1; off < 32; off <<= 1) {
        const int v = __shfl_down_sync(0xFFFFFFFFu, suf, off);
        if (lane + off < 32) suf += v;
    }
    int suf_next = __shfl_down_sync(0xFFFFFFFFu, suf, 1);
    if (lane == 31) suf_next = 0;
    if (suf_next < target && target <= suf) {       // exactly one lane
        int cumAbove = suf_next;
        #pragma unroll
        for (int j = 7; j >= 0; --j) {
            const int h = hist[lane * 8 + j];
            if (cumAbove < target && target <= cumAbove + h) {
                *out_b = lane * 8 + j;
                *out_r = target - cumAbove;
                break;
            }
            cumAbove += h;
        }
    }
}

__global__ void reset_queue_kernel() { g_next = 0; }

// ---------------------------------------------------------------------------
// Persistent work-stealing pipelines: each 256-thread half fetches graph ids
// from a global queue and runs the full fused per-graph pipeline with its own
// named barrier. Every SM hosts 4 independent pipelines -> phases overlap and
// load balances by time, not by static CTA count.
// ---------------------------------------------------------------------------
__global__ void __launch_bounds__(CTA_T, 2)
sagpool_fused_kernel(const float* __restrict__ x,
                     const int*   __restrict__ edge_index,
                     const float* __restrict__ gcn_w,
                     const float* __restrict__ gcn_b,
                     const float* __restrict__ lin_w,
                     const float* __restrict__ lin_b,
                     float*       __restrict__ out,
                     int E_total)
{
    extern __shared__ __align__(16) unsigned char smem_raw[];
    SmemHalf* sh = reinterpret_cast<SmemHalf*>(smem_raw);

    const int tid  = threadIdx.x;
    const int half = tid >> 8;            // 0 or 1
    const int gtid = tid & (GT - 1);      // 0..255 within pipeline
    const int wid  = gtid >> 5;           // 0..7
    const int lane = gtid & 31;
    const int bar  = half + 1;            // named barrier id

    SmemHalf* s = sh + half;

    for (;;) {
        // ---- fetch next graph; reset per-graph state ----
        if (gtid == 0) {
            s->gid  = atomicAdd(&g_next, 1);
            s->ovfn = 0;
        }
        s->cnt[gtid] = 0;
        GBAR(bar);
        const int g = s->gid;
        if (g >= NG) break;

        // ---- Head: xw gemv + edge bucket scatter (order staggered per half) ----
        {
            const float4 wv = reinterpret_cast<const float4*>(gcn_w)[lane];
            const float4* xg = reinterpret_cast<const float4*>(x + (size_t)g * N_PER * DD);
            const int4* s4 = reinterpret_cast<const int4*>(edge_index + (size_t)g * E_PER);
            const int4* d4 = reinterpret_cast<const int4*>(edge_index + (size_t)E_total + (size_t)g * E_PER);

            auto xw_chunk = [&](int it) {
                #pragma unroll
                for (int ii = 0; ii < 8; ++ii) {
                    const int node = wid * 32 + it * 8 + ii;
                    const float4 v = xg[node * (DD / 4) + lane];
                    float d = v.x * wv.x + v.y * wv.y + v.z * wv.z + v.w * wv.w;
                    #pragma unroll
                    for (int off = 16; off; off >>= 1)
                        d += __shfl_down_sync(0xFFFFFFFFu, d, off);
                    if (lane == 0) s->xwp[node] = d;
                }
            };
            auto scatter_chunk = [&](int it) {
                const int ei = it * GT + gtid;
                const int4 ss = __ldcs(s4 + ei);          // read-once, evict-first
                const int4 dd = __ldcs(d4 + ei);
                #pragma unroll
                for (int e = 0; e < 4; ++e) {
                    const int a = ((&ss.x)[e]) & (N_PER - 1);
                    const int b = ((&dd.x)[e]) & (N_PER - 1);
                    const int pos = atomicAdd(&s->cnt[b], 1);
                    if (pos < MAXB) {
                        s->bkt[b * BSTR + pos] = (unsigned short)a;
                    } else {
                        const int k = atomicAdd(&s->ovfn, 1);
                        if (k < OVF_CAP) s->ovf[k] = (b << 16) | a;
                    }
                }
            };

            if (half == 0) {                   // interleaved
                #pragma unroll
                for (int it = 0; it < 4; ++it) { scatter_chunk(it); xw_chunk(it); }
            } else {                           // scatter-all first, then stream x
                #pragma unroll
                for (int it = 0; it < 4; ++it) scatter_chunk(it);
                #pragma unroll
                for (int it = 0; it < 4; ++it) xw_chunk(it);
            }
        }
        GBAR(bar);

        // ---- dinv; pre-scale xwp = xw * dinv ----
        const int mdeg = s->cnt[gtid];
        {
            const float dv = rsqrtf((float)(mdeg + 1));        // +1 self-loop
            s->dinv[gtid] = dv;
            s->xwp[gtid] *= dv;
        }
        GBAR(bar);

        // ---- Atomic-free gather (vectorized indices, MLP-16 xwp loads) ----
        {
            const int m = min(mdeg, MAXB);
            const uint4* row4 = reinterpret_cast<const uint4*>(s->bkt + gtid * BSTR);
            const uint4 ra = row4[0];                          // indices 0..7
            const uint4 rb = row4[1];                          // indices 8..15
            int id[16];
            id[0]  = ra.x & 0xFFFF; id[1]  = ra.x >> 16;
            id[2]  = ra.y & 0xFFFF; id[3]  = ra.y >> 16;
            id[4]  = ra.z & 0xFFFF; id[5]  = ra.z >> 16;
            id[6]  = ra.w & 0xFFFF; id[7]  = ra.w >> 16;
            id[8]  = rb.x & 0xFFFF; id[9]  = rb.x >> 16;
            id[10] = rb.y & 0xFFFF; id[11] = rb.y >> 16;
            id[12] = rb.z & 0xFFFF; id[13] = rb.z >> 16;
            id[14] = rb.w & 0xFFFF; id[15] = rb.w >> 16;
            float sum = 0.0f;
            #pragma unroll
            for (int j = 0; j < 16; ++j)
                if (j < m) sum += s->xwp[id[j]];
            for (int j = 16; j < m; ++j)                       // rare tail (deg > 16)
                sum += s->xwp[s->bkt[gtid * BSTR + j]];
            s->agg[gtid] = sum;
        }
        GBAR(bar);

        // ---- Rare overflow edges (degree > MAXB) via shared atomics ----
        {
            const int n = min(s->ovfn, OVF_CAP);
            for (int i = gtid; i < n; i += GT) {
                const int e = s->ovf[i];
                atomicAdd(&s->agg[e >> 16], s->xwp[e & 0xFFFF]);
            }
        }
        GBAR(bar);

        // ---- score + gate + sortable key ----
        unsigned int ub;
        {
            const float sc = s->dinv[gtid] * (s->agg[gtid] + s->xwp[gtid]) + __ldg(gcn_b);
            s->gate[gtid] = tanhf(sc);
            unsigned int u = __float_as_uint(sc);
            ub = (u & 0x80000000u) ? ~u : (u | 0x80000000u);   // monotone map
            s->m[gtid] = ub;
        }

        // ---- radix-select top-K: pass 1 (byte 1) ----
        s->cnt[gtid] = 0;
        GBAR(bar);
        atomicAdd(&s->cnt[ub >> 24], 1);
        GBAR(bar);
        if (wid == 0) radix_scan256(s->cnt, KK, &s->sel[0], &s->sel[1], lane);
        GBAR(bar);
        const int b1 = s->sel[0];
        const int r1 = s->sel[1];
        const int c1 = s->cnt[b1];                              // boundary bucket size
        const int byte1 = (int)(ub >> 24);
        bool keep = (byte1 > b1);
        bool cand = (byte1 == b1);
        int  target = r1;

        // ---- optional pass 2 (byte 2) only when boundary bucket is large ----
        if (c1 > 96) {
            GBAR(bar);                         // everyone read c1/hist before reuse
            s->cnt[gtid] = 0;
            GBAR(bar);
            if (cand) atomicAdd(&s->cnt[(ub >> 16) & 255], 1);
            GBAR(bar);
            if (wid == 0) radix_scan256(s->cnt, r1, &s->sel[2], &s->sel[3], lane);
            GBAR(bar);
            const int b2 = s->sel[2];
            const int byte2 = (int)((ub >> 16) & 255);
            keep   = keep || (cand && byte2 > b2);
            cand   = cand && (byte2 == b2);
            target = s->sel[3];
        }

        // ---- exact stable rank among the (small) candidate set ----
        {
            const unsigned ball = __ballot_sync(0xFFFFFFFFu, cand);
            if (lane == 0) s->woff[wid] = __popc(ball);
            GBAR(bar);
            if (gtid == 0) {
                int acc = 0;
                #pragma unroll
                for (int w = 0; w < 8; ++w) { const int c = s->woff[w]; s->woff[w] = acc; acc += c; }
                s->sel[4] = acc;
            }
            GBAR(bar);
            if (cand) {
                const int pos = s->woff[wid] + __popc(ball & ((1u << lane) - 1u));
                s->cand[pos] = (unsigned short)gtid;
            }
            GBAR(bar);
            if (cand) {
                const int c = s->sel[4];
                int rank = 0;
                for (int j = 0; j < c; ++j) {
                    const int idx = s->cand[j];
                    const unsigned int mj = s->m[idx];
                    rank += (mj > ub) || (mj == ub && idx < gtid);
                }
                keep = (rank < target);
            }
        }
        GBAR(bar);

        // ---- compact kept node ids (exactly KK of them) ----
        {
            const unsigned ball = __ballot_sync(0xFFFFFFFFu, keep);
            if (lane == 0) s->woff[wid] = __popc(ball);
            GBAR(bar);
            if (gtid == 0) {
                int acc = 0;
                #pragma unroll
                for (int w = 0; w < 8; ++w) { const int c = s->woff[w]; s->woff[w] = acc; acc += c; }
            }
            GBAR(bar);
            if (keep) {
                const int pos = s->woff[wid] + __popc(ball & ((1u << lane) - 1u));
                s->kept[pos] = (unsigned short)gtid;
            }
        }
        GBAR(bar);

        // ---- gated mean/max pooling over the 128 kept rows (L2 re-read) ----
        {
            const float4* xb = reinterpret_cast<const float4*>(x + (size_t)g * N_PER * DD) + lane;
            float4 sum = make_float4(0.f, 0.f, 0.f, 0.f);
            float4 mx  = make_float4(-CUDART_INF_F, -CUDART_INF_F, -CUDART_INF_F, -CUDART_INF_F);
            #pragma unroll 4
            for (int j = 0; j < KK / 8; ++j) {      // 16 kept nodes per warp
                const int n = s->kept[wid * (KK / 8) + j];
                const float gt = s->gate[n];
                const float4 v = xb[n * (DD / 4)];
                const float vx = v.x * gt, vy = v.y * gt, vz = v.z * gt, vw = v.w * gt;
                sum.x += vx; sum.y += vy; sum.z += vz; sum.w += vw;
                mx.x = fmaxf(mx.x, vx); mx.y = fmaxf(mx.y, vy);
                mx.z = fmaxf(mx.z, vz); mx.w = fmaxf(mx.w, vw);
            }
            s->psum4[wid][lane] = sum;
            s->pmax4[wid][lane] = mx;
        }
        GBAR(bar);

        // ---- reduce pooling partials into readout [mean | max] ----
        if (gtid < 32) {
            float4 a = s->psum4[0][gtid];
            #pragma unroll
            for (int q = 1; q < 8; ++q) {
                const float4 b = s->psum4[q][gtid];
                a.x += b.x; a.y += b.y; a.z += b.z; a.w += b.w;
            }
            const float inv = 1.0f / (float)KK;
            a.x *= inv; a.y *= inv; a.z *= inv; a.w *= inv;
            reinterpret_cast<float4*>(s->read)[gtid] = a;
        } else if (gtid < 64) {
            const int t = gtid - 32;
            float4 a = s->pmax4[0][t];
            #pragma unroll
            for (int q = 1; q < 8; ++q) {
                const float4 b = s->pmax4[q][t];
                a.x = fmaxf(a.x, b.x); a.y = fmaxf(a.y, b.y);
                a.z = fmaxf(a.z, b.z); a.w = fmaxf(a.w, b.w);
            }
            reinterpret_cast<float4*>(s->read + DD)[t] = a;
        }
        GBAR(bar);

        // ---- fused linear epilogue (float4 warp k-slabs) ----
        {
            const float4* w4 = reinterpret_cast<const float4*>(lin_w);  // [2DD][DD/4]
            float4 acc = make_float4(0.f, 0.f, 0.f, 0.f);
            const int k0 = wid * 32;                    // 8 warps x 32 k each
            #pragma unroll 8
            for (int k = 0; k < 32; ++k) {
                const float r = s->read[k0 + k];        // LDS broadcast
                const float4 wv = __ldg(&w4[(k0 + k) * (DD / 4) + lane]);
                acc.x = fmaf(r, wv.x, acc.x);
                acc.y = fmaf(r, wv.y, acc.y);
                acc.z = fmaf(r, wv.z, acc.z);
                acc.w = fmaf(r, wv.w, acc.w);
            }
            s->psum4[wid][lane] = acc;                  // reuse pooling partials
        }
        GBAR(bar);
        if (gtid < 32) {
            float4 a = s->psum4[0][gtid];
            #pragma unroll
            for (int q = 1; q < 8; ++q) {
                const float4 b = s->psum4[q][gtid];
                a.x += b.x; a.y += b.y; a.z += b.z; a.w += b.w;
            }
            const float4 bb = reinterpret_cast<const float4*>(lin_b)[gtid];
            a.x += bb.x; a.y += bb.y; a.z += bb.z; a.w += bb.w;
            reinterpret_cast<float4*>(out + g * DD)[gtid] = a;
        }
        GBAR(bar);   // body complete before next gid fetch reuses shared state
    }
}

// ---------------------------------------------------------------------------
extern "C" void kernel_launch(void* const* d_in, const int* in_sizes, int n_in,
                              void* d_out, int out_size)
{
    const float* x     = (const float*)d_in[0];  // [N, D]
    // d_in[1] = graph_indicator (unused; equal-size contiguous graphs)
    const int*   ei    = (const int*)  d_in[2];  // [2, E]
    const float* gcn_w = (const float*)d_in[3];  // [D, 1]
    const float* gcn_b = (const float*)d_in[4];  // [1]
    const float* lin_w = (const float*)d_in[5];  // [2D, D]
    const float* lin_b = (const float*)d_in[6];  // [D]
    float*       out   = (float*)d_out;          // [G, D]

    const int E_total = in_sizes[2] / 2;
    const int smem = 2 * (int)sizeof(SmemHalf);

    cudaFuncSetAttribute(sagpool_fused_kernel,
                         cudaFuncAttributeMaxDynamicSharedMemorySize, smem);

    reset_queue_kernel<<<1, 1>>>();
    sagpool_fused_kernel<<<GRID_B, CTA_T, smem>>>(
        x, ei, gcn_w, gcn_b, lin_w, lin_b, out, E_total);
}

// round 13
// speedup vs baseline: 1.1015x; 1.1015x over previous
#include <cuda_runtime.h>
#include <math_constants.h>

// Problem constants (fixed by the dataset)
#define NG      512     // graphs
#define N_PER   256     // nodes per graph
#define DD      128     // embed dim
#define E_PER   4096    // edges per graph
#define KK      128     // kept nodes per graph
#define GT      256     // threads per graph-group (half CTA)
#define CTA_T   512     // threads per CTA (2 pipelines)
#define MAXB    36      // bucket capacity (max in-degree w/o overflow)
#define BSTR    40      // bucket row stride in ushorts (80 B, 16B-aligned rows)
#define OVF_CAP 256     // overflow edge list capacity

// Per-pipeline shared state. float4 arrays first for alignment.
struct SmemHalf {
    float4 psum4[8][DD / 4];           // 4 KB (pooling + epilogue partials)
    float4 pmax4[8][DD / 4];           // 4 KB
    unsigned short bkt[N_PER * BSTR];  // 20.5 KB CSR buckets (16B-aligned rows)
    int   cnt[N_PER];                  // in-degree / cursor
    int   hist[N_PER];                 // radix histogram (separate from cnt)
    float xwp[N_PER];                  // xw, then xw*dinv
    float dinv[N_PER];
    float agg[N_PER];                  // edge sum, then score
    float gate[N_PER];
    unsigned int   m[N_PER];           // sortable score keys
    float read[2 * DD];                // readout [mean | max]
    int   ovf[OVF_CAP];                // packed (dst<<16)|src
    unsigned short cand[N_PER];        // boundary candidates (unordered)
    unsigned short kept[KK];           // compacted kept node ids (stable order)
    int   woff[8];                     // per-warp compaction offsets
    int   sel[4];                      // b1, r1, b2, r2
    int   ovfn;
    int   candn;
};

// Named barrier over one 256-thread pipeline (ids 1 and 2).
#define GBAR(id) asm volatile("bar.sync %0, %1;" :: "r"(id), "r"(GT) : "memory")

// Warp-0-of-half helper: given hist[256], find bucket b* and residual r such
// that suffix(b*+1) < target <= suffix(b*);  r = target - suffix(b*+1).
__device__ __forceinline__ void radix_scan256(const int* hist, int target,
                                              int* out_b, int* out_r, int lane)
{
    int s = 0;
    #pragma unroll
    for (int j = 0; j < 8; ++j) s += hist[lane * 8 + j];
    int suf = s;                                    // inclusive suffix over chunks
    #pragma unroll
    for (int off = 1; off < 32; off <<= 1) {
        const int v = __shfl_down_sync(0xFFFFFFFFu, suf, off);
        if (lane + off < 32) suf += v;
    }
    int suf_next = __shfl_down_sync(0xFFFFFFFFu, suf, 1);
    if (lane == 31) suf_next = 0;
    if (suf_next < target && target <= suf) {       // exactly one lane
        int cumAbove = suf_next;
        #pragma unroll
        for (int j = 7; j >= 0; --j) {
            const int h = hist[lane * 8 + j];
            if (cumAbove < target && target <= cumAbove + h) {
                *out_b = lane * 8 + j;
                *out_r = target - cumAbove;
                break;
            }
            cumAbove += h;
        }
    }
}

// ---------------------------------------------------------------------------
// Two graphs per CTA; each 256-thread half runs a full fused pipeline with
// its own named barrier (halves drift out of phase -> DRAM/LSU/ALU overlap).
// ---------------------------------------------------------------------------
__global__ void __launch_bounds__(CTA_T, 2)
sagpool_fused_kernel(const float* __restrict__ x,
                     const int*   __restrict__ edge_index,
                     const float* __restrict__ gcn_w,
                     const float* __restrict__ gcn_b,
                     const float* __restrict__ lin_w,
                     const float* __restrict__ lin_b,
                     float*       __restrict__ out,
                     int E_total)
{
    extern __shared__ __align__(16) unsigned char smem_raw[];
    SmemHalf* sh = reinterpret_cast<SmemHalf*>(smem_raw);

    const int tid  = threadIdx.x;
    const int half = tid >> 8;            // 0 or 1
    const int gtid = tid & (GT - 1);      // 0..255 within pipeline
    const int wid  = gtid >> 5;           // 0..7
    const int lane = gtid & 31;
    const int bar  = half + 1;            // named barrier id
    const int g    = blockIdx.x * 2 + half;

    SmemHalf* s = sh + half;

    s->cnt[gtid]  = 0;
    s->hist[gtid] = 0;
    if (gtid == 0) { s->ovfn = 0; s->candn = 0; }
    GBAR(bar);

    // ---- Head: xw gemv + edge bucket scatter (order staggered per half) ----
    {
        const float4 wv = reinterpret_cast<const float4*>(gcn_w)[lane];
        const float4* xg = reinterpret_cast<const float4*>(x + (size_t)g * N_PER * DD);
        const int4* s4 = reinterpret_cast<const int4*>(edge_index + (size_t)g * E_PER);
        const int4* d4 = reinterpret_cast<const int4*>(edge_index + (size_t)E_total + (size_t)g * E_PER);

        auto xw_chunk = [&](int it) {
            #pragma unroll
            for (int ii = 0; ii < 8; ++ii) {
                const int node = wid * 32 + it * 8 + ii;
                const float4 v = xg[node * (DD / 4) + lane];
                float d = v.x * wv.x + v.y * wv.y + v.z * wv.z + v.w * wv.w;
                #pragma unroll
                for (int off = 16; off; off >>= 1)
                    d += __shfl_down_sync(0xFFFFFFFFu, d, off);
                if (lane == 0) s->xwp[node] = d;
            }
        };
        auto scatter_chunk = [&](int it) {
            const int ei = it * GT + gtid;
            const int4 ss = __ldcs(s4 + ei);          // read-once, evict-first
            const int4 dd = __ldcs(d4 + ei);
            #pragma unroll
            for (int e = 0; e < 4; ++e) {
                const int a = ((&ss.x)[e]) & (N_PER - 1);
                const int b = ((&dd.x)[e]) & (N_PER - 1);
                const int pos = atomicAdd(&s->cnt[b], 1);
                if (pos < MAXB) {
                    s->bkt[b * BSTR + pos] = (unsigned short)a;
                } else {
                    const int k = atomicAdd(&s->ovfn, 1);
                    if (k < OVF_CAP) s->ovf[k] = (b << 16) | a;
                }
            }
        };

        if (half == 0) {                   // interleaved
            #pragma unroll
            for (int it = 0; it < 4; ++it) { scatter_chunk(it); xw_chunk(it); }
        } else {                           // scatter-all first, then stream x
            #pragma unroll
            for (int it = 0; it < 4; ++it) scatter_chunk(it);
            #pragma unroll
            for (int it = 0; it < 4; ++it) xw_chunk(it);
        }
    }
    GBAR(bar);

    // ---- dinv; pre-scale xwp = xw * dinv ----
    const int mdeg = s->cnt[gtid];
    {
        const float dv = rsqrtf((float)(mdeg + 1));        // +1 self-loop
        s->dinv[gtid] = dv;
        s->xwp[gtid] *= dv;
    }
    GBAR(bar);

    // ---- Atomic-free gather (vectorized indices, MLP-16 xwp loads) ----
    {
        const int m = min(mdeg, MAXB);
        const uint4* row4 = reinterpret_cast<const uint4*>(s->bkt + gtid * BSTR);
        const uint4 ra = row4[0];                          // indices 0..7
        const uint4 rb = row4[1];                          // indices 8..15
        int id[16];
        id[0]  = ra.x & 0xFFFF; id[1]  = ra.x >> 16;
        id[2]  = ra.y & 0xFFFF; id[3]  = ra.y >> 16;
        id[4]  = ra.z & 0xFFFF; id[5]  = ra.z >> 16;
        id[6]  = ra.w & 0xFFFF; id[7]  = ra.w >> 16;
        id[8]  = rb.x & 0xFFFF; id[9]  = rb.x >> 16;
        id[10] = rb.y & 0xFFFF; id[11] = rb.y >> 16;
        id[12] = rb.z & 0xFFFF; id[13] = rb.z >> 16;
        id[14] = rb.w & 0xFFFF; id[15] = rb.w >> 16;
        float sum = 0.0f;
        #pragma unroll
        for (int j = 0; j < 16; ++j)
            if (j < m) sum += s->xwp[id[j]];
        for (int j = 16; j < m; ++j)                       // rare tail (deg > 16)
            sum += s->xwp[s->bkt[gtid * BSTR + j]];
        s->agg[gtid] = sum;
    }
    GBAR(bar);

    // ---- Rare overflow edges (degree > MAXB); barrier only when present ----
    {
        const int n = min(s->ovfn, OVF_CAP);               // uniform across pipeline
        if (n > 0) {
            for (int i = gtid; i < n; i += GT) {
                const int e = s->ovf[i];
                atomicAdd(&s->agg[e >> 16], s->xwp[e & 0xFFFF]);
            }
            GBAR(bar);
        }
    }

    // ---- score + gate + sortable key; radix pass-1 histogram ----
    unsigned int ub;
    {
        const float sc = s->dinv[gtid] * (s->agg[gtid] + s->xwp[gtid]) + __ldg(gcn_b);
        s->gate[gtid] = tanhf(sc);
        unsigned int u = __float_as_uint(sc);
        ub = (u & 0x80000000u) ? ~u : (u | 0x80000000u);   // monotone map
        s->m[gtid] = ub;
    }
    atomicAdd(&s->hist[ub >> 24], 1);                      // hist pre-zeroed at init
    GBAR(bar);
    if (wid == 0) radix_scan256(s->hist, KK, &s->sel[0], &s->sel[1], lane);
    GBAR(bar);
    const int b1 = s->sel[0];
    const int r1 = s->sel[1];
    const int c1 = s->hist[b1];                             // boundary bucket size
    const int byte1 = (int)(ub >> 24);
    bool keep = (byte1 > b1);
    bool cand = (byte1 == b1);
    int  target = r1;

    // ---- optional pass 2 (byte 2) only when boundary bucket is large ----
    if (c1 > 96) {
        GBAR(bar);                         // everyone read c1/hist before reuse
        s->hist[gtid] = 0;
        GBAR(bar);
        if (cand) atomicAdd(&s->hist[(ub >> 16) & 255], 1);
        GBAR(bar);
        if (wid == 0) radix_scan256(s->hist, r1, &s->sel[2], &s->sel[3], lane);
        GBAR(bar);
        const int b2 = s->sel[2];
        const int byte2 = (int)((ub >> 16) & 255);
        keep   = keep || (cand && byte2 > b2);
        cand   = cand && (byte2 == b2);
        target = s->sel[3];
    }

    // ---- exact stable rank among candidates (unordered placement is fine:
    //      the rank is an order-independent integer count) ----
    if (cand) {
        const int pos = atomicAdd(&s->candn, 1);
        s->cand[pos] = (unsigned short)gtid;
    }
    GBAR(bar);
    if (cand) {
        const int c = s->candn;
        int rank = 0;
        for (int j = 0; j < c; ++j) {
            const int idx = s->cand[j];
            const unsigned int mj = s->m[idx];
            rank += (mj > ub) || (mj == ub && idx < gtid);
        }
        keep = (rank < target);
    }
    GBAR(bar);

    // ---- compact kept node ids (stable order: deterministic pooling sums) ----
    {
        const unsigned ball = __ballot_sync(0xFFFFFFFFu, keep);
        if (lane == 0) s->woff[wid] = __popc(ball);
        GBAR(bar);
        if (gtid == 0) {
            int acc = 0;
            #pragma unroll
            for (int w = 0; w < 8; ++w) { const int c = s->woff[w]; s->woff[w] = acc; acc += c; }
        }
        GBAR(bar);
        if (keep) {
            const int pos = s->woff[wid] + __popc(ball & ((1u << lane) - 1u));
            s->kept[pos] = (unsigned short)gtid;
        }
    }
    GBAR(bar);

    // ---- gated mean/max pooling over the 128 kept rows (L2 re-read) ----
    {
        const float4* xb = reinterpret_cast<const float4*>(x + (size_t)g * N_PER * DD) + lane;
        float4 sum = make_float4(0.f, 0.f, 0.f, 0.f);
        float4 mx  = make_float4(-CUDART_INF_F, -CUDART_INF_F, -CUDART_INF_F, -CUDART_INF_F);
        #pragma unroll 4
        for (int j = 0; j < KK / 8; ++j) {      // 16 kept nodes per warp
            const int n = s->kept[wid * (KK / 8) + j];
            const float gt = s->gate[n];
            const float4 v = xb[n * (DD / 4)];
            const float vx = v.x * gt, vy = v.y * gt, vz = v.z * gt, vw = v.w * gt;
            sum.x += vx; sum.y += vy; sum.z += vz; sum.w += vw;
            mx.x = fmaxf(mx.x, vx); mx.y = fmaxf(mx.y, vy);
            mx.z = fmaxf(mx.z, vz); mx.w = fmaxf(mx.w, vw);
        }
        s->psum4[wid][lane] = sum;
        s->pmax4[wid][lane] = mx;
    }
    GBAR(bar);

    // ---- reduce pooling partials into readout [mean | max] ----
    if (gtid < 32) {
        float4 a = s->psum4[0][gtid];
        #pragma unroll
        for (int q = 1; q < 8; ++q) {
            const float4 b = s->psum4[q][gtid];
            a.x += b.x; a.y += b.y; a.z += b.z; a.w += b.w;
        }
        const float inv = 1.0f / (float)KK;
        a.x *= inv; a.y *= inv; a.z *= inv; a.w *= inv;
        reinterpret_cast<float4*>(s->read)[gtid] = a;
    } else if (gtid < 64) {
        const int t = gtid - 32;
        float4 a = s->pmax4[0][t];
        #pragma unroll
        for (int q = 1; q < 8; ++q) {
            const float4 b = s->pmax4[q][t];
            a.x = fmaxf(a.x, b.x); a.y = fmaxf(a.y, b.y);
            a.z = fmaxf(a.z, b.z); a.w = fmaxf(a.w, b.w);
        }
        reinterpret_cast<float4*>(s->read + DD)[t] = a;
    }
    GBAR(bar);

    // ---- fused linear epilogue (float4 warp k-slabs) ----
    {
        const float4* w4 = reinterpret_cast<const float4*>(lin_w);  // [2DD][DD/4]
        float4 acc = make_float4(0.f, 0.f, 0.f, 0.f);
        const int k0 = wid * 32;                    // 8 warps x 32 k each
        #pragma unroll 8
        for (int k = 0; k < 32; ++k) {
            const float r = s->read[k0 + k];        // LDS broadcast
            const float4 wv = __ldg(&w4[(k0 + k) * (DD / 4) + lane]);
            acc.x = fmaf(r, wv.x, acc.x);
            acc.y = fmaf(r, wv.y, acc.y);
            acc.z = fmaf(r, wv.z, acc.z);
            acc.w = fmaf(r, wv.w, acc.w);
        }
        s->psum4[wid][lane] = acc;                  // reuse pooling partials
    }
    GBAR(bar);
    if (gtid < 32) {
        float4 a = s->psum4[0][gtid];
        #pragma unroll
        for (int q = 1; q < 8; ++q) {
            const float4 b = s->psum4[q][gtid];
            a.x += b.x; a.y += b.y; a.z += b.z; a.w += b.w;
        }
        const float4 bb = reinterpret_cast<const float4*>(lin_b)[gtid];
        a.x += bb.x; a.y += bb.y; a.z += bb.z; a.w += bb.w;
        reinterpret_cast<float4*>(out + g * DD)[gtid] = a;
    }
}

// ---------------------------------------------------------------------------
extern "C" void kernel_launch(void* const* d_in, const int* in_sizes, int n_in,
                              void* d_out, int out_size)
{
    const float* x     = (const float*)d_in[0];  // [N, D]
    // d_in[1] = graph_indicator (unused; equal-size contiguous graphs)
    const int*   ei    = (const int*)  d_in[2];  // [2, E]
    const float* gcn_w = (const float*)d_in[3];  // [D, 1]
    const float* gcn_b = (const float*)d_in[4];  // [1]
    const float* lin_w = (const float*)d_in[5];  // [2D, D]
    const float* lin_b = (const float*)d_in[6];  // [D]
    float*       out   = (float*)d_out;          // [G, D]

    const int E_total = in_sizes[2] / 2;
    const int smem = 2 * (int)sizeof(SmemHalf);

    cudaFuncSetAttribute(sagpool_fused_kernel,
                         cudaFuncAttributeMaxDynamicSharedMemorySize, smem);

    sagpool_fused_kernel<<<NG / 2, CTA_T, smem>>>(
        x, ei, gcn_w, gcn_b, lin_w, lin_b, out, E_total);
}